// round 16
// baseline (speedup 1.0000x reference)
#include <cuda_runtime.h>

// ChamferLoss via uniform-grid exact nearest neighbor. B=4, N=M=8192, 3D.
// Brute force is pinned at the fp32 fma floor (~55us); the grid makes NN local:
// bin both sets into 48^3 cells (H=0.25 over [-6,6]), counting-sort, then each
// query scans Chebyshev rings k=0,1,... stopping when ((k-1)H)^2 > best.
// Exact min (conservative bound), ~77 candidates/query avg vs 8192.

#define BB 4
#define NP 8192
#define GD 48
#define NCELLS (GD * GD * GD)        // 110592
#define XMIN (-6.0f)
#define H 0.25f
#define INVH 4.0f
#define NSETS 8                      // (set, batch)
#define TOTQ (NSETS * NP)            // 65536
#define SCAN_T 1024
#define CPT (NCELLS / SCAN_T)        // 108

__device__ int g_cnt[NSETS][NCELLS];
__device__ int g_off[NSETS][NCELLS + 1];
__device__ int g_cur[NSETS][NCELLS];
__device__ float4 g_pts[NSETS][NP];

__device__ __forceinline__ int cell_of(float x, float y, float z) {
    int cx = (int)((x - XMIN) * INVH); cx = min(max(cx, 0), GD - 1);
    int cy = (int)((y - XMIN) * INVH); cy = min(max(cy, 0), GD - 1);
    int cz = (int)((z - XMIN) * INVH); cz = min(max(cz, 0), GD - 1);
    return (cz * GD + cy) * GD + cx;
}

// K1: zero counts + out[0]
__global__ void zero_kernel(float* out) {
    int4* dst = (int4*)g_cnt[0];
    const int tot = NSETS * NCELLS / 4;
    for (int k = blockIdx.x * blockDim.x + threadIdx.x; k < tot;
         k += gridDim.x * blockDim.x)
        dst[k] = make_int4(0, 0, 0, 0);
    if (blockIdx.x == 0 && threadIdx.x == 0) out[0] = 0.f;
}

// K2: histogram both point sets into cells
__global__ void count_kernel(const float* __restrict__ xyz1,
                             const float* __restrict__ xyz2) {
    int gid = blockIdx.x * blockDim.x + threadIdx.x;   // 0..65535
    int set = gid >> 15;
    int r = gid & 32767;
    int b = r >> 13;
    int i = r & (NP - 1);
    const float* p = (set ? xyz2 : xyz1) + ((size_t)(b * NP + i)) * 3;
    int c = cell_of(p[0], p[1], p[2]);
    atomicAdd(&g_cnt[set * 4 + b][c], 1);
}

// K3: per-(set,b) exclusive scan -> offsets (+ cursor copy). 8 blocks x 1024.
__global__ void scan_kernel() {
    const int bs = blockIdx.x;
    const int tid = threadIdx.x;
    const int base = tid * CPT;
    int s = 0;
    for (int c = 0; c < CPT; c++) s += g_cnt[bs][base + c];
    __shared__ int sh[SCAN_T];
    sh[tid] = s;
    __syncthreads();
    for (int o = 1; o < SCAN_T; o <<= 1) {   // Hillis-Steele inclusive
        int v = (tid >= o) ? sh[tid - o] : 0;
        __syncthreads();
        sh[tid] += v;
        __syncthreads();
    }
    int run = sh[tid] - s;                    // exclusive prefix
    for (int c = 0; c < CPT; c++) {
        int cc = base + c;
        g_off[bs][cc] = run;
        g_cur[bs][cc] = run;
        run += g_cnt[bs][cc];
    }
    if (tid == SCAN_T - 1) g_off[bs][NCELLS] = run;   // == NP
}

// K4: scatter points into cell-sorted SoA (float4)
__global__ void scatter_kernel(const float* __restrict__ xyz1,
                               const float* __restrict__ xyz2) {
    int gid = blockIdx.x * blockDim.x + threadIdx.x;
    int set = gid >> 15;
    int r = gid & 32767;
    int b = r >> 13;
    int i = r & (NP - 1);
    int bs = set * 4 + b;
    const float* p = (set ? xyz2 : xyz1) + ((size_t)(b * NP + i)) * 3;
    float x = p[0], y = p[1], z = p[2];
    int c = cell_of(x, y, z);
    int pos = atomicAdd(&g_cur[bs][c], 1);
    g_pts[bs][pos] = make_float4(x, y, z, 0.f);
}

// K5: exact NN search, both directions. 65536 threads (cell-sorted queries).
__global__ void __launch_bounds__(256) search_kernel(float* __restrict__ out) {
    int gid = blockIdx.x * blockDim.x + threadIdx.x;   // 0..65535
    int combo = gid >> 13;                              // 0..7
    int idx = gid & (NP - 1);
    int b = combo & 3;
    int qset = combo >> 2;
    int qbs = qset * 4 + b;
    int dbs = (1 - qset) * 4 + b;
    float4 q = g_pts[qbs][idx];
    const float4* __restrict__ db = g_pts[dbs];
    const int* __restrict__ off = g_off[dbs];

    int qx = (int)((q.x - XMIN) * INVH); qx = min(max(qx, 0), GD - 1);
    int qy = (int)((q.y - XMIN) * INVH); qy = min(max(qy, 0), GD - 1);
    int qz = (int)((q.z - XMIN) * INVH); qz = min(max(qz, 0), GD - 1);

    float best = 3.4e38f;
    for (int k = 0; k < GD; k++) {
        if (k >= 2) {
            float lb = (float)(k - 1) * H;
            if (lb * lb > best) break;   // no closer point possible in ring >= k
        }
        int zlo = max(qz - k, 0), zhi = min(qz + k, GD - 1);
        for (int cz = zlo; cz <= zhi; cz++) {
            int adz = cz - qz; adz = adz < 0 ? -adz : adz;
            int ylo = max(qy - k, 0), yhi = min(qy + k, GD - 1);
            for (int cy = ylo; cy <= yhi; cy++) {
                int ady = cy - qy; ady = ady < 0 ? -ady : ady;
                int rowb = (cz * GD + cy) * GD;
                if (adz == k || ady == k) {
                    // full x-row of the ring: contiguous cells -> one range
                    int xlo = max(qx - k, 0), xhi = min(qx + k, GD - 1);
                    int s0 = off[rowb + xlo], s1 = off[rowb + xhi + 1];
                    for (int p = s0; p < s1; p++) {
                        float4 v = db[p];
                        float dx = q.x - v.x, dy = q.y - v.y, dz = q.z - v.z;
                        float d = fmaf(dx, dx, fmaf(dy, dy, dz * dz));
                        best = fminf(best, d);
                    }
                } else {
                    int cx0 = qx - k, cx1 = qx + k;
                    if (cx0 >= 0) {
                        int c = rowb + cx0;
                        int s0 = off[c], s1 = off[c + 1];
                        for (int p = s0; p < s1; p++) {
                            float4 v = db[p];
                            float dx = q.x - v.x, dy = q.y - v.y, dz = q.z - v.z;
                            float d = fmaf(dx, dx, fmaf(dy, dy, dz * dz));
                            best = fminf(best, d);
                        }
                    }
                    if (cx1 < GD) {
                        int c = rowb + cx1;
                        int s0 = off[c], s1 = off[c + 1];
                        for (int p = s0; p < s1; p++) {
                            float4 v = db[p];
                            float dx = q.x - v.x, dy = q.y - v.y, dz = q.z - v.z;
                            float d = fmaf(dx, dx, fmaf(dy, dy, dz * dz));
                            best = fminf(best, d);
                        }
                    }
                }
            }
        }
    }

    // sum of all 65536 bests / 32768 == mean(d1) + mean(d2)
    float s = best * (1.f / (BB * NP));
#pragma unroll
    for (int o = 16; o > 0; o >>= 1)
        s += __shfl_down_sync(0xffffffffu, s, o);
    __shared__ float sh[8];
    int lane = threadIdx.x & 31, warp = threadIdx.x >> 5;
    if (lane == 0) sh[warp] = s;
    __syncthreads();
    if (warp == 0) {
        float v = (lane < 8) ? sh[lane] : 0.f;
#pragma unroll
        for (int o = 4; o > 0; o >>= 1)
            v += __shfl_down_sync(0xffu, v, o);
        if (lane == 0) atomicAdd(out, v);
    }
}

extern "C" void kernel_launch(void* const* d_in, const int* in_sizes, int n_in,
                              void* d_out, int out_size) {
    const float* xyz1 = (const float*)d_in[0];
    const float* xyz2 = (const float*)d_in[1];
    float* out = (float*)d_out;

    zero_kernel<<<256, 256>>>(out);
    count_kernel<<<TOTQ / 256, 256>>>(xyz1, xyz2);
    scan_kernel<<<NSETS, SCAN_T>>>();
    scatter_kernel<<<TOTQ / 256, 256>>>(xyz1, xyz2);
    search_kernel<<<TOTQ / 256, 256>>>(out);
}

// round 17
// speedup vs baseline: 2.6952x; 2.6952x over previous
#include <cuda_runtime.h>

// ChamferLoss via bounded uniform-grid NN + warp-cooperative fixup.
// B=4, N=M=8192, 3D. Grid 32^3, H=0.25 over [-4,4] (clamped, distance-safe).
// Phase A: rings 0-1 (9 rows). Exact if best <= H^2.
// Phase B: full 5x5x5 (25 rows). Exact if best <= (2H)^2.
// Else: query id -> fail list; fixup kernel brute-forces 1 warp/query.
// Constant per-thread work everywhere -> no straggler warps (R16 killer).

#define BB 4
#define NP 8192
#define GD 32
#define NCELLS (GD * GD * GD)       // 32768
#define XMIN (-4.0f)
#define H 0.25f
#define INVH 4.0f
#define NSETS 8                     // (set, batch)
#define TOTQ (NSETS * NP)           // 65536
#define SCAN_T 1024
#define CPT (NCELLS / SCAN_T)       // 32
#define MAXFAIL TOTQ
#define SCALE (1.0f / (BB * NP))

__device__ int g_cnt[NSETS][NCELLS];
__device__ int g_off[NSETS][NCELLS + 1];
__device__ int g_cur[NSETS][NCELLS];
__device__ float4 g_pts[NSETS][NP];
__device__ int g_fail[MAXFAIL];
__device__ int g_nfail;

__device__ __forceinline__ int cell_clamp(float f) {
    int c = (int)f;
    return min(max(c, 0), GD - 1);
}

// K1: histogram points into cells; also zero out[0] / fail counter.
__global__ void count_kernel(const float* __restrict__ xyz1,
                             const float* __restrict__ xyz2,
                             float* __restrict__ out) {
    int gid = blockIdx.x * blockDim.x + threadIdx.x;
    if (gid == 0) { out[0] = 0.f; g_nfail = 0; }
    int set = gid >> 15, r = gid & 32767, b = r >> 13, i = r & (NP - 1);
    const float* p = (set ? xyz2 : xyz1) + ((size_t)(b * NP + i)) * 3;
    int cx = cell_clamp((p[0] - XMIN) * INVH);
    int cy = cell_clamp((p[1] - XMIN) * INVH);
    int cz = cell_clamp((p[2] - XMIN) * INVH);
    atomicAdd(&g_cnt[set * 4 + b][(cz * GD + cy) * GD + cx], 1);
}

// K2: per-(set,b) exclusive scan. 8 blocks x 1024 threads, CPT=32 cells each.
__global__ void scan_kernel() {
    const int bs = blockIdx.x, tid = threadIdx.x, base = tid * CPT;
    int s = 0;
    for (int c = 0; c < CPT; c++) s += g_cnt[bs][base + c];
    __shared__ int sh[SCAN_T];
    sh[tid] = s;
    __syncthreads();
    for (int o = 1; o < SCAN_T; o <<= 1) {
        int v = (tid >= o) ? sh[tid - o] : 0;
        __syncthreads();
        sh[tid] += v;
        __syncthreads();
    }
    int run = sh[tid] - s;
    for (int c = 0; c < CPT; c++) {
        int cc = base + c;
        g_off[bs][cc] = run;
        g_cur[bs][cc] = run;
        run += g_cnt[bs][cc];
    }
    if (tid == SCAN_T - 1) g_off[bs][NCELLS] = run;
}

// K3: scatter points cell-sorted; then re-zero g_cnt for the next replay.
__global__ void scatter_kernel(const float* __restrict__ xyz1,
                               const float* __restrict__ xyz2) {
    int gid = blockIdx.x * blockDim.x + threadIdx.x;
    int set = gid >> 15, r = gid & 32767, b = r >> 13, i = r & (NP - 1);
    int bs = set * 4 + b;
    const float* p = (set ? xyz2 : xyz1) + ((size_t)(b * NP + i)) * 3;
    float x = p[0], y = p[1], z = p[2];
    int cx = cell_clamp((x - XMIN) * INVH);
    int cy = cell_clamp((y - XMIN) * INVH);
    int cz = cell_clamp((z - XMIN) * INVH);
    int pos = atomicAdd(&g_cur[bs][(cz * GD + cy) * GD + cx], 1);
    g_pts[bs][pos] = make_float4(x, y, z, 0.f);
    // zero counts for next launch (262144 ints / 65536 threads = int4 each)
    ((int4*)g_cnt)[gid] = make_int4(0, 0, 0, 0);
}

__device__ __forceinline__ void scan_row(const float4* __restrict__ db,
                                         int s0, int s1, float qx, float qy,
                                         float qz, float& best) {
    for (int p = s0; p < s1; p++) {
        float4 v = db[p];
        float dx = qx - v.x, dy = qy - v.y, dz = qz - v.z;
        best = fminf(best, fmaf(dx, dx, fmaf(dy, dy, dz * dz)));
    }
}

// K4: bounded search. Ring 0-1 (9 rows) -> maybe 5x5x5 (25 rows) -> else fail.
__global__ void __launch_bounds__(256) search_kernel(float* __restrict__ out) {
    int gid = blockIdx.x * blockDim.x + threadIdx.x;
    int combo = gid >> 13, idx = gid & (NP - 1);
    int b = combo & 3, qset = combo >> 2;
    float4 q = g_pts[qset * 4 + b][idx];
    const int dbs = (1 - qset) * 4 + b;
    const float4* __restrict__ db = g_pts[dbs];
    const int* __restrict__ off = g_off[dbs];

    float fx = (q.x - XMIN) * INVH, fy = (q.y - XMIN) * INVH, fz = (q.z - XMIN) * INVH;
    bool oob = (fx < 0.f) | (fx >= (float)GD) | (fy < 0.f) | (fy >= (float)GD)
             | (fz < 0.f) | (fz >= (float)GD);
    int cx = cell_clamp(fx), cy = cell_clamp(fy), cz = cell_clamp(fz);

    float best = 3.4e38f;
    // Phase A: rings 0-1
    {
        int zlo = max(cz - 1, 0), zhi = min(cz + 1, GD - 1);
        int ylo = max(cy - 1, 0), yhi = min(cy + 1, GD - 1);
        int xlo = max(cx - 1, 0), xhi = min(cx + 1, GD - 1);
        for (int z = zlo; z <= zhi; z++)
            for (int y = ylo; y <= yhi; y++) {
                int rowb = (z * GD + y) * GD;
                scan_row(db, off[rowb + xlo], off[rowb + xhi + 1],
                         q.x, q.y, q.z, best);
            }
    }
    bool done = (!oob) && (best <= H * H);
    if (!done) {
        // Phase B: full 5x5x5 (interior rescans are idempotent for min)
        int zlo = max(cz - 2, 0), zhi = min(cz + 2, GD - 1);
        int ylo = max(cy - 2, 0), yhi = min(cy + 2, GD - 1);
        int xlo = max(cx - 2, 0), xhi = min(cx + 2, GD - 1);
        for (int z = zlo; z <= zhi; z++)
            for (int y = ylo; y <= yhi; y++) {
                int rowb = (z * GD + y) * GD;
                scan_row(db, off[rowb + xlo], off[rowb + xhi + 1],
                         q.x, q.y, q.z, best);
            }
        done = (!oob) && (best <= (2.f * H) * (2.f * H));
        if (!done) {
            g_fail[atomicAdd(&g_nfail, 1)] = gid;   // exact answer via fixup
        }
    }

    float s = done ? best * SCALE : 0.f;
#pragma unroll
    for (int o = 16; o > 0; o >>= 1) s += __shfl_down_sync(0xffffffffu, s, o);
    __shared__ float sh[8];
    int lane = threadIdx.x & 31, warp = threadIdx.x >> 5;
    if (lane == 0) sh[warp] = s;
    __syncthreads();
    if (warp == 0) {
        float v = (lane < 8) ? sh[lane] : 0.f;
#pragma unroll
        for (int o = 4; o > 0; o >>= 1) v += __shfl_down_sync(0xffu, v, o);
        if (lane == 0) atomicAdd(out, v);
    }
}

// K5: fixup — one warp per failed query, brute force over all NP, REDUX.MIN.
__global__ void fixup_kernel(float* __restrict__ out) {
    int lane = threadIdx.x & 31;
    int gw = (blockIdx.x * blockDim.x + threadIdx.x) >> 5;   // 0..511
    int nf = g_nfail;
    for (int f = gw; f < nf; f += 512) {
        int gid = g_fail[f];
        int combo = gid >> 13, idx = gid & (NP - 1);
        int b = combo & 3, qset = combo >> 2;
        float4 q = g_pts[qset * 4 + b][idx];
        const float4* __restrict__ db = g_pts[(1 - qset) * 4 + b];
        float best = 3.4e38f;
        for (int p = lane; p < NP; p += 32) {
            float4 v = db[p];
            float dx = q.x - v.x, dy = q.y - v.y, dz = q.z - v.z;
            best = fminf(best, fmaf(dx, dx, fmaf(dy, dy, dz * dz)));
        }
        int bi = __reduce_min_sync(0xffffffffu, __float_as_int(best)); // >=0 -> s32 order ok
        if (lane == 0) atomicAdd(out, __int_as_float(bi) * SCALE);
    }
}

extern "C" void kernel_launch(void* const* d_in, const int* in_sizes, int n_in,
                              void* d_out, int out_size) {
    const float* xyz1 = (const float*)d_in[0];
    const float* xyz2 = (const float*)d_in[1];
    float* out = (float*)d_out;

    count_kernel<<<TOTQ / 256, 256>>>(xyz1, xyz2, out);
    scan_kernel<<<NSETS, SCAN_T>>>();
    scatter_kernel<<<TOTQ / 256, 256>>>(xyz1, xyz2);
    search_kernel<<<TOTQ / 256, 256>>>(out);
    fixup_kernel<<<64, 256>>>(out);
}